// round 16
// baseline (speedup 1.0000x reference)
#include <cuda_runtime.h>
#include <cuda_bf16.h>
#include <math_constants.h>
#include <stdint.h>

// Problem constants (fixed shapes per reference)
#define MAXN 50048
#define MAXE 400000
#define DD   256

// packed weight layout (rows are output-features, k contiguous):
//   layer i (i=0..2) at i*262144 : rows 0:256=Wq^T, 256:512=Wk^T, 512:768=Wv^T, 768:1024=(Ws+linW)^T
//   final at 786432 : rows 0:64=fWq^T, 64:128=fWk^T, 128:192=fWv^T, 192:208=(fWs+flinW)^T
#define WOFF_F   786432
#define WTOTAL   (WOFF_F + 208 * 256)
#define BTOTAL   (3 * 1024 + 208)

// ---------------- scratch (static device globals; no allocs) ----------------
__device__ float g_big [MAXN * 1024];   // per-layer q|k|v|sl (stride 1024); final [N,208]
__device__ float g_agg [MAXN * DD];
__device__ __nv_bfloat16 g_hhi[MAXN * DD];
__device__ __nv_bfloat16 g_hlo[MAXN * DD];
__device__ __nv_bfloat16 g_whi[WTOTAL];
__device__ __nv_bfloat16 g_wlo[WTOTAL];
__device__ float g_bias[BTOTAL];
__device__ int   g_deg   [MAXN];
__device__ int   g_rowptr[MAXN + 1];
__device__ int   g_cursor[MAXN];
__device__ int   g_col   [MAXE];
__device__ int   g_hist  [64];
__device__ int   g_hcur  [64];
__device__ int   g_perm  [MAXN];

// ---------------- CSR build ----------------
__global__ void zero_int_kernel(int* p, int n) {
    int i = blockIdx.x * blockDim.x + threadIdx.x;
    if (i < n) p[i] = 0;
}

__global__ void count_deg_kernel(const int* __restrict__ dst, int* deg, int E) {
    int i = blockIdx.x * blockDim.x + threadIdx.x;
    if (i < E) atomicAdd(&deg[dst[i]], 1);
}

// exclusive scan; writes rowptr AND cursor
__global__ void exscan_kernel(const int* __restrict__ deg, int* rowptr, int* cursor, int n) {
    __shared__ int warpsums[32];
    __shared__ int carry_s;
    int tid = threadIdx.x, lane = tid & 31, wid = tid >> 5;
    if (tid == 0) carry_s = 0;
    __syncthreads();
    for (int base = 0; base < n; base += 1024) {
        int carry = carry_s;
        int i = base + tid;
        int v = (i < n) ? deg[i] : 0;
        int x = v;
        #pragma unroll
        for (int o = 1; o < 32; o <<= 1) {
            int y = __shfl_up_sync(0xffffffffu, x, o);
            if (lane >= o) x += y;
        }
        if (lane == 31) warpsums[wid] = x;
        __syncthreads();
        if (wid == 0) {
            int s = warpsums[lane];
            #pragma unroll
            for (int o = 1; o < 32; o <<= 1) {
                int y = __shfl_up_sync(0xffffffffu, s, o);
                if (lane >= o) s += y;
            }
            warpsums[lane] = s;
        }
        __syncthreads();
        int block_excl = (wid > 0) ? warpsums[wid - 1] : 0;
        int incl = x + block_excl;
        if (i < n) {
            int val = carry + incl - v;
            rowptr[i] = val;
            cursor[i] = val;
        }
        int total = warpsums[31];
        __syncthreads();
        if (tid == 0) carry_s = carry + total;
        __syncthreads();
    }
    if (tid == 0) rowptr[n] = carry_s;
}

__global__ void scatter_kernel(const int* __restrict__ src, const int* __restrict__ dst,
                               int* cursor, int* col, int E) {
    int i = blockIdx.x * blockDim.x + threadIdx.x;
    if (i < E) {
        int d = dst[i];
        int pos = atomicAdd(&cursor[d], 1);
        col[pos] = src[i];
    }
}

// ---------------- degree-sorted node permutation (counting sort, 64 bins) ----------------
__global__ void hist_deg_kernel(const int* __restrict__ deg, int* hist, int n) {
    int i = blockIdx.x * blockDim.x + threadIdx.x;
    if (i < n) {
        int b = deg[i]; if (b > 63) b = 63;
        atomicAdd(&hist[b], 1);
    }
}

// exclusive scan of 64 bins with one warp (2 elems/lane); writes cursor
__global__ void scan64_kernel(const int* __restrict__ hist, int* bincur) {
    int lane = threadIdx.x & 31;
    int v0 = hist[2 * lane], v1 = hist[2 * lane + 1];
    int s = v0 + v1;
    int x = s;
    #pragma unroll
    for (int o = 1; o < 32; o <<= 1) {
        int y = __shfl_up_sync(0xffffffffu, x, o);
        if (lane >= o) x += y;
    }
    int excl = x - s;
    bincur[2 * lane] = excl;
    bincur[2 * lane + 1] = excl + v0;
}

__global__ void scatter_perm_kernel(const int* __restrict__ deg, int* bincur,
                                    int* perm, int n) {
    int i = blockIdx.x * blockDim.x + threadIdx.x;
    if (i < n) {
        int b = deg[i]; if (b > 63) b = 63;
        int pos = atomicAdd(&bincur[b], 1);
        perm[pos] = i;
    }
}

// ---------------- conversions ----------------
__device__ __forceinline__ void bf16_split(float f, __nv_bfloat16& h, __nv_bfloat16& l) {
    h = __float2bfloat16(f);
    l = __float2bfloat16(f - __bfloat162float(h));
}

__global__ void convert_x_kernel(const float* __restrict__ in,
                                 __nv_bfloat16* __restrict__ hi,
                                 __nv_bfloat16* __restrict__ lo, int n) {
    int i = blockIdx.x * blockDim.x + threadIdx.x;
    if (i < n) {
        __nv_bfloat16 h, l;
        bf16_split(in[i], h, l);
        hi[i] = h; lo[i] = l;
    }
}

struct WPtrs {
    const float *Wq, *Wk, *Wv, *Ws, *linW;
    const float *fWq, *fWk, *fWv, *fWs, *flinW;
};

__global__ void convert_weights_kernel(WPtrs p, __nv_bfloat16* __restrict__ hi,
                                       __nv_bfloat16* __restrict__ lo) {
    int idx = blockIdx.x * blockDim.x + threadIdx.x;
    if (idx >= WTOTAL) return;
    float val;
    if (idx < WOFF_F) {
        int layer = idx >> 18;
        int rem = idx & 262143;
        int r = rem >> 8;
        int kk = rem & 255;
        int slot = r >> 8;
        int m = r & 255;
        size_t o = (size_t)layer * 65536 + (size_t)kk * 256 + m;
        if (slot == 0)      val = p.Wq[o];
        else if (slot == 1) val = p.Wk[o];
        else if (slot == 2) val = p.Wv[o];
        else                val = p.Ws[o] + p.linW[o];
    } else {
        int f = idx - WOFF_F;
        int r = f >> 8;
        int kk = f & 255;
        if (r < 64)       val = p.fWq[(size_t)kk * 64 + r];
        else if (r < 128) val = p.fWk[(size_t)kk * 64 + (r - 64)];
        else if (r < 192) val = p.fWv[(size_t)kk * 64 + (r - 128)];
        else              val = p.fWs[(size_t)kk * 16 + (r - 192)]
                              + p.flinW[(size_t)kk * 16 + (r - 192)];
    }
    __nv_bfloat16 h, l;
    bf16_split(val, h, l);
    hi[idx] = h; lo[idx] = l;
}

struct BPtrs {
    const float *bq, *bk, *bv, *bs, *linB;
    const float *fbq, *fbk, *fbv, *fbs, *flinB;
};

__global__ void pack_bias_kernel(BPtrs p, float* __restrict__ out) {
    int idx = blockIdx.x * blockDim.x + threadIdx.x;
    if (idx >= BTOTAL) return;
    float val;
    if (idx < 3072) {
        int layer = idx >> 10;
        int r = idx & 1023;
        int slot = r >> 8;
        int c = r & 255;
        int o = layer * 256 + c;
        if (slot == 0)      val = p.bq[o];
        else if (slot == 1) val = p.bk[o];
        else if (slot == 2) val = p.bv[o];
        else                val = p.bs[o] + p.linB[o];
    } else {
        int f = idx - 3072;
        if (f < 64)       val = p.fbq[f];
        else if (f < 128) val = p.fbk[f - 64];
        else if (f < 192) val = p.fbv[f - 128];
        else              val = p.fbs[f - 192] + p.flinB[f - 192];
    }
    out[idx] = val;
}

// ---------------- cp.async helpers ----------------
__device__ __forceinline__ void cp16(uint32_t saddr, const void* gaddr, bool pred) {
    int sz = pred ? 16 : 0;
    asm volatile("cp.async.ca.shared.global [%0], [%1], 16, %2;\n"
                 :: "r"(saddr), "l"(gaddr), "r"(sz));
}
__device__ __forceinline__ void cp_commit() {
    asm volatile("cp.async.commit_group;\n" ::: "memory");
}
template <int NN>
__device__ __forceinline__ void cp_wait() {
    asm volatile("cp.async.wait_group %0;\n" :: "n"(NN) : "memory");
}

// ---------------- mma.sync bf16x3 GEMM (R12 proven body) ----------------
#define TBM    128
#define ROW_W  20
#define A_W    (128 * ROW_W)
#define SMEM_WORDS (8 * A_W)

__device__ __forceinline__ void mma_bf16(float c[4], uint32_t a0, uint32_t a1,
                                         uint32_t a2, uint32_t a3,
                                         uint32_t b0, uint32_t b1) {
    asm volatile(
        "mma.sync.aligned.m16n8k16.row.col.f32.bf16.bf16.f32 "
        "{%0,%1,%2,%3}, {%4,%5,%6,%7}, {%8,%9}, {%0,%1,%2,%3};\n"
        : "+f"(c[0]), "+f"(c[1]), "+f"(c[2]), "+f"(c[3])
        : "r"(a0), "r"(a1), "r"(a2), "r"(a3), "r"(b0), "r"(b1));
}

__device__ __forceinline__ void ldsm_x4(uint32_t& d0, uint32_t& d1, uint32_t& d2,
                                        uint32_t& d3, uint32_t addr) {
    asm volatile("ldmatrix.sync.aligned.m8n8.x4.shared.b16 {%0,%1,%2,%3}, [%4];"
                 : "=r"(d0), "=r"(d1), "=r"(d2), "=r"(d3) : "r"(addr));
}

__global__ void __launch_bounds__(256, 2)
gemm_bf16x3_kernel(const __nv_bfloat16* __restrict__ Xhi, const __nv_bfloat16* __restrict__ Xlo,
                   const __nv_bfloat16* __restrict__ Whi, const __nv_bfloat16* __restrict__ Wlo,
                   const float* __restrict__ bias, float* __restrict__ Y,
                   int Nrows, int Mcols) {
    extern __shared__ uint32_t smw[];
    uint32_t base_u = (uint32_t)__cvta_generic_to_shared(smw);

    int tid = threadIdx.x;
    int lane = tid & 31, wid = tid >> 5;
    int rowTile = blockIdx.x * TBM;
    int colTile = blockIdx.y * 128;
    int warpRow = (wid & 3) * 32;
    int warpCol = (wid >> 2) * 64;

    float acc[2][8][4];
    #pragma unroll
    for (int mf = 0; mf < 2; mf++)
        #pragma unroll
        for (int nf = 0; nf < 8; nf++)
            #pragma unroll
            for (int i = 0; i < 4; i++) acc[mf][nf][i] = 0.f;

    auto stage = [&](int t, int buf) {
        int k0 = t * 32;
        #pragma unroll
        for (int i = 0; i < 2; i++) {
            int ch = tid + i * 256;
            int r = ch >> 2;
            int c = ch & 3;
            bool aok = (rowTile + r) < Nrows;
            size_t goff = (size_t)(rowTile + r) * 256 + k0 + c * 8;
            uint32_t soff = (uint32_t)(buf * A_W + r * ROW_W + c * 4) * 4u;
            cp16(base_u + soff, Xhi + goff, aok);
            cp16(base_u + (uint32_t)(2 * A_W) * 4u + soff, Xlo + goff, aok);
            bool bok = (colTile + r) < Mcols;
            size_t gboff = (size_t)(colTile + r) * 256 + k0 + c * 8;
            cp16(base_u + (uint32_t)(4 * A_W) * 4u + soff, Whi + gboff, bok);
            cp16(base_u + (uint32_t)(6 * A_W) * 4u + soff, Wlo + gboff, bok);
        }
        cp_commit();
    };

    stage(0, 0);

    int a_row = lane & 15;
    int a_wsel = (lane >> 4) << 2;
    int b_row = ((lane >> 4) << 3) + (lane & 7);
    int b_wsel = ((lane >> 3) & 1) << 2;

    const int NT = 8;
    for (int t = 0; t < NT; t++) {
        int buf = t & 1;
        cp_wait<0>();
        __syncthreads();
        if (t + 1 < NT) stage(t + 1, buf ^ 1);

        uint32_t AHb = base_u + (uint32_t)(buf * A_W) * 4u;
        uint32_t ALb = base_u + (uint32_t)(2 * A_W + buf * A_W) * 4u;
        uint32_t BHb = base_u + (uint32_t)(4 * A_W + buf * A_W) * 4u;
        uint32_t BLb = base_u + (uint32_t)(6 * A_W + buf * A_W) * 4u;

        #pragma unroll
        for (int s = 0; s < 2; s++) {
            int kb = s * 8;
            uint32_t ahi[2][4], alo[2][4];
            #pragma unroll
            for (int mf = 0; mf < 2; mf++) {
                uint32_t off = (uint32_t)((warpRow + mf * 16 + a_row) * ROW_W
                                          + kb + a_wsel) * 4u;
                ldsm_x4(ahi[mf][0], ahi[mf][1], ahi[mf][2], ahi[mf][3], AHb + off);
                ldsm_x4(alo[mf][0], alo[mf][1], alo[mf][2], alo[mf][3], ALb + off);
            }
            #pragma unroll
            for (int p = 0; p < 4; p++) {
                uint32_t off = (uint32_t)((warpCol + p * 16 + b_row) * ROW_W
                                          + kb + b_wsel) * 4u;
                uint32_t bh0a, bh1a, bh0b, bh1b;
                uint32_t bl0a, bl1a, bl0b, bl1b;
                ldsm_x4(bh0a, bh1a, bh0b, bh1b, BHb + off);
                ldsm_x4(bl0a, bl1a, bl0b, bl1b, BLb + off);
                #pragma unroll
                for (int mf = 0; mf < 2; mf++) {
                    mma_bf16(acc[mf][2 * p], ahi[mf][0], ahi[mf][1], ahi[mf][2], ahi[mf][3], bh0a, bh1a);
                    mma_bf16(acc[mf][2 * p], ahi[mf][0], ahi[mf][1], ahi[mf][2], ahi[mf][3], bl0a, bl1a);
                    mma_bf16(acc[mf][2 * p], alo[mf][0], alo[mf][1], alo[mf][2], alo[mf][3], bh0a, bh1a);
                }
                #pragma unroll
                for (int mf = 0; mf < 2; mf++) {
                    mma_bf16(acc[mf][2 * p + 1], ahi[mf][0], ahi[mf][1], ahi[mf][2], ahi[mf][3], bh0b, bh1b);
                    mma_bf16(acc[mf][2 * p + 1], ahi[mf][0], ahi[mf][1], ahi[mf][2], ahi[mf][3], bl0b, bl1b);
                    mma_bf16(acc[mf][2 * p + 1], alo[mf][0], alo[mf][1], alo[mf][2], alo[mf][3], bh0b, bh1b);
                }
            }
        }
    }

    #pragma unroll
    for (int mf = 0; mf < 2; mf++) {
        #pragma unroll
        for (int nf = 0; nf < 8; nf++) {
            int col = colTile + warpCol + nf * 8 + 2 * (lane & 3);
            if (col >= Mcols) continue;
            float bx = bias[col], by = bias[col + 1];
            int r0 = rowTile + warpRow + mf * 16 + (lane >> 2);
            if (r0 < Nrows) {
                float2 o = make_float2(acc[mf][nf][0] + bx, acc[mf][nf][1] + by);
                *(float2*)&Y[(size_t)r0 * Mcols + col] = o;
            }
            int r1 = r0 + 8;
            if (r1 < Nrows) {
                float2 o = make_float2(acc[mf][nf][2] + bx, acc[mf][nf][3] + by);
                *(float2*)&Y[(size_t)r1 * Mcols + col] = o;
            }
        }
    }
}

// ---------------- edge attention (layers): warp per node (degree-sorted) ----------------
// Max-free streaming softmax (shift-invariant; scores O(5), exp safe).
__global__ void edge_attn_kernel(const float* __restrict__ big,
                                 const int* __restrict__ rowptr, const int* __restrict__ col,
                                 const int* __restrict__ perm,
                                 float* __restrict__ agg, int Nn) {
    int gw = (blockIdx.x * blockDim.x + threadIdx.x) >> 5;
    int lane = threadIdx.x & 31;
    if (gw >= Nn) return;
    int node = perm[gw];
    const float* qrow = big + (size_t)node * 1024 + lane * 8;
    float4 qa = *(const float4*)qrow;
    float4 qb = *(const float4*)(qrow + 4);
    int e0 = rowptr[node], e1 = rowptr[node + 1];
    float ssum = 0.f;
    float4 acca = make_float4(0.f, 0.f, 0.f, 0.f);
    float4 accb = make_float4(0.f, 0.f, 0.f, 0.f);
    for (int e = e0; e < e1; e++) {
        int src = col[e];
        const float* kr = big + (size_t)src * 1024 + 256 + lane * 8;
        float4 ka = *(const float4*)kr;
        float4 kb = *(const float4*)(kr + 4);
        float4 va = *(const float4*)(kr + 256);
        float4 vb = *(const float4*)(kr + 260);
        float part = qa.x * ka.x + qa.y * ka.y + qa.z * ka.z + qa.w * ka.w
                   + qb.x * kb.x + qb.y * kb.y + qb.z * kb.z + qb.w * kb.w;
        part += __shfl_xor_sync(0xffffffffu, part, 1);
        part += __shfl_xor_sync(0xffffffffu, part, 2);
        part += __shfl_xor_sync(0xffffffffu, part, 4);
        float pr = __expf(part * 0.125f);      // 1/sqrt(64)
        ssum += pr;
        acca.x += pr * va.x;
        acca.y += pr * va.y;
        acca.z += pr * va.z;
        acca.w += pr * va.w;
        accb.x += pr * vb.x;
        accb.y += pr * vb.y;
        accb.z += pr * vb.z;
        accb.w += pr * vb.w;
    }
    float inv = (ssum > 0.f) ? (1.f / ssum) : 0.f;
    acca.x *= inv; acca.y *= inv; acca.z *= inv; acca.w *= inv;
    accb.x *= inv; accb.y *= inv; accb.z *= inv; accb.w *= inv;
    float* arow = agg + (size_t)node * 256 + lane * 8;
    *(float4*)arow = acca;
    *(float4*)(arow + 4) = accb;
}

// ---------------- combine + elu + layernorm -> split bf16 hi/lo ----------------
__global__ void combine_ln_kernel(const float* __restrict__ agg, const float* __restrict__ big,
                                  const float* __restrict__ g, const float* __restrict__ b,
                                  __nv_bfloat16* __restrict__ hhi,
                                  __nv_bfloat16* __restrict__ hlo, int Nn) {
    int node = (blockIdx.x * blockDim.x + threadIdx.x) >> 5;
    int lane = threadIdx.x & 31;
    if (node >= Nn) return;
    int base = node * 256;
    const float* sl = big + (size_t)node * 1024 + 768;
    float t[8];
    float sum = 0.f;
    #pragma unroll
    for (int r = 0; r < 8; r++) {
        int j = r * 32 + lane;
        float c = agg[base + j] + sl[j];
        float e = (c > 0.f) ? c : expm1f(c);
        t[r] = e; sum += e;
    }
    #pragma unroll
    for (int o = 16; o > 0; o >>= 1) sum += __shfl_xor_sync(0xffffffffu, sum, o);
    float mu = sum * (1.f / 256.f);
    float var = 0.f;
    #pragma unroll
    for (int r = 0; r < 8; r++) { float d = t[r] - mu; var += d * d; }
    #pragma unroll
    for (int o = 16; o > 0; o >>= 1) var += __shfl_xor_sync(0xffffffffu, var, o);
    var *= (1.f / 256.f);
    float inv = rsqrtf(var + 1e-5f);
    #pragma unroll
    for (int r = 0; r < 8; r++) {
        int j = r * 32 + lane;
        float val = (t[r] - mu) * inv * g[j] + b[j];
        __nv_bfloat16 h, l;
        bf16_split(val, h, l);
        hhi[base + j] = h;
        hlo[base + j] = l;
    }
}

// ---------------- final edge attention: warp per node (degree-sorted) ----------------
__global__ void edge_attn_final_kernel(const float* __restrict__ big,
                                       const int* __restrict__ rowptr, const int* __restrict__ col,
                                       const int* __restrict__ perm,
                                       float* __restrict__ agg, int Nn) {
    int gw = (blockIdx.x * blockDim.x + threadIdx.x) >> 5;
    int lane = threadIdx.x & 31;
    if (gw >= Nn) return;
    int node = perm[gw];
    float2 q2 = *(const float2*)(big + (size_t)node * 208 + lane * 2);
    int e0 = rowptr[node], e1 = rowptr[node + 1];
    float ssum = 0.f;
    float2 acc = make_float2(0.f, 0.f);
    for (int e = e0; e < e1; e++) {
        int src = col[e];
        const float* srow = big + (size_t)src * 208;
        float2 k2 = *(const float2*)(srow + 64 + lane * 2);
        float2 v2 = *(const float2*)(srow + 128 + lane * 2);
        float part = q2.x * k2.x + q2.y * k2.y;
        part += __shfl_xor_sync(0xffffffffu, part, 1);
        part += __shfl_xor_sync(0xffffffffu, part, 2);
        part += __shfl_xor_sync(0xffffffffu, part, 4);
        float pr = __expf(part * 0.25f);       // 1/sqrt(16)
        ssum += pr;
        acc.x += pr * v2.x;
        acc.y += pr * v2.y;
    }
    float inv = (ssum > 0.f) ? (1.f / ssum) : 0.f;
    acc.x *= inv; acc.y *= inv;
    *(float2*)(agg + (size_t)node * 64 + lane * 2) = acc;
}

// ---------------- final combine: mean heads + sl + LN(16) ----------------
__global__ void final_combine_kernel(const float* __restrict__ aggF, const float* __restrict__ big,
                                     const float* __restrict__ g, const float* __restrict__ b,
                                     float* __restrict__ out, int Nn) {
    int t = blockIdx.x * blockDim.x + threadIdx.x;
    int node = t >> 4;
    int c = t & 15;
    if (node >= Nn) return;
    const float* ar = aggF + (size_t)node * 64;
    float val = 0.25f * (ar[c] + ar[16 + c] + ar[32 + c] + ar[48 + c])
              + big[(size_t)node * 208 + 192 + c];
    float sum = val;
    #pragma unroll
    for (int o = 8; o > 0; o >>= 1) sum += __shfl_xor_sync(0xffffffffu, sum, o);
    float mu = sum * (1.f / 16.f);
    float d = val - mu;
    float var = d * d;
    #pragma unroll
    for (int o = 8; o > 0; o >>= 1) var += __shfl_xor_sync(0xffffffffu, var, o);
    var *= (1.f / 16.f);
    out[node * 16 + c] = (val - mu) * rsqrtf(var + 1e-5f) * g[c] + b[c];
}

// ---------------- host launch ----------------
static inline int cdiv(int a, int b) { return (a + b - 1) / b; }

extern "C" void kernel_launch(void* const* d_in, const int* in_sizes, int n_in,
                              void* d_out, int out_size) {
    const float* x    = (const float*)d_in[0];
    const int*   ei   = (const int*)  d_in[1];
    const float* Wq   = (const float*)d_in[2];
    const float* bq   = (const float*)d_in[3];
    const float* Wk   = (const float*)d_in[4];
    const float* bk   = (const float*)d_in[5];
    const float* Wv   = (const float*)d_in[6];
    const float* bv   = (const float*)d_in[7];
    const float* Ws   = (const float*)d_in[8];
    const float* bs   = (const float*)d_in[9];
    const float* lnG  = (const float*)d_in[10];
    const float* lnB  = (const float*)d_in[11];
    const float* linW = (const float*)d_in[12];
    const float* linB = (const float*)d_in[13];
    const float* fWq  = (const float*)d_in[14];
    const float* fbq  = (const float*)d_in[15];
    const float* fWk  = (const float*)d_in[16];
    const float* fbk  = (const float*)d_in[17];
    const float* fWv  = (const float*)d_in[18];
    const float* fbv  = (const float*)d_in[19];
    const float* fWs  = (const float*)d_in[20];
    const float* fbs  = (const float*)d_in[21];
    const float* flnG = (const float*)d_in[22];
    const float* flnB = (const float*)d_in[23];
    const float* flinW= (const float*)d_in[24];
    const float* flinB= (const float*)d_in[25];
    float* out = (float*)d_out;

    int N = in_sizes[0] / DD;     // 50000
    int E = in_sizes[1] / 2;      // 400000

    cudaFuncSetAttribute(gemm_bf16x3_kernel,
                         cudaFuncAttributeMaxDynamicSharedMemorySize, SMEM_WORDS * 4);

    float *p_big, *p_agg, *p_bias;
    __nv_bfloat16 *p_hhi, *p_hlo, *p_whi, *p_wlo;
    int *p_deg, *p_rowptr, *p_cursor, *p_col, *p_hist, *p_hcur, *p_perm;
    cudaGetSymbolAddress((void**)&p_big,  g_big);
    cudaGetSymbolAddress((void**)&p_agg,  g_agg);
    cudaGetSymbolAddress((void**)&p_bias, g_bias);
    cudaGetSymbolAddress((void**)&p_hhi,  g_hhi);
    cudaGetSymbolAddress((void**)&p_hlo,  g_hlo);
    cudaGetSymbolAddress((void**)&p_whi,  g_whi);
    cudaGetSymbolAddress((void**)&p_wlo,  g_wlo);
    cudaGetSymbolAddress((void**)&p_deg,    g_deg);
    cudaGetSymbolAddress((void**)&p_rowptr, g_rowptr);
    cudaGetSymbolAddress((void**)&p_cursor, g_cursor);
    cudaGetSymbolAddress((void**)&p_col,    g_col);
    cudaGetSymbolAddress((void**)&p_hist,   g_hist);
    cudaGetSymbolAddress((void**)&p_hcur,   g_hcur);
    cudaGetSymbolAddress((void**)&p_perm,   g_perm);

    const int* src = ei;
    const int* dst = ei + E;

    // --- conversions first, then layer-0 GEMM (keeps GEMM in the ncu slot) ---
    WPtrs wp = { Wq, Wk, Wv, Ws, linW, fWq, fWk, fWv, fWs, flinW };
    convert_weights_kernel<<<cdiv(WTOTAL, 256), 256>>>(wp, p_whi, p_wlo);
    BPtrs bp = { bq, bk, bv, bs, linB, fbq, fbk, fbv, fbs, flinB };
    pack_bias_kernel<<<cdiv(BTOTAL, 256), 256>>>(bp, p_bias);
    convert_x_kernel<<<cdiv(N * DD, 256), 256>>>(x, p_hhi, p_hlo, N * DD);

    {   // layer-0 projections
        dim3 grid(cdiv(N, TBM), 8);
        gemm_bf16x3_kernel<<<grid, 256, SMEM_WORDS * 4>>>(
            p_hhi, p_hlo, p_whi, p_wlo, p_bias, p_big, N, 1024);
    }

    // --- CSR build (by dst) + degree-sorted permutation ---
    zero_int_kernel<<<cdiv(N, 256), 256>>>(p_deg, N);
    count_deg_kernel<<<cdiv(E, 256), 256>>>(dst, p_deg, E);
    exscan_kernel<<<1, 1024>>>(p_deg, p_rowptr, p_cursor, N);
    scatter_kernel<<<cdiv(E, 256), 256>>>(src, dst, p_cursor, p_col, E);
    zero_int_kernel<<<1, 64>>>(p_hist, 64);
    hist_deg_kernel<<<cdiv(N, 256), 256>>>(p_deg, p_hist, N);
    scan64_kernel<<<1, 32>>>(p_hist, p_hcur);
    scatter_perm_kernel<<<cdiv(N, 256), 256>>>(p_deg, p_hcur, p_perm, N);

    // --- 3 TransformerConv layers (layer 0 GEMM already issued) ---
    for (int i = 0; i < 3; i++) {
        if (i > 0) {
            dim3 grid(cdiv(N, TBM), 8);
            gemm_bf16x3_kernel<<<grid, 256, SMEM_WORDS * 4>>>(
                p_hhi, p_hlo,
                p_whi + (size_t)i * 262144, p_wlo + (size_t)i * 262144,
                p_bias + i * 1024, p_big, N, 1024);
        }
        edge_attn_kernel<<<cdiv(N * 32, 256), 256>>>(p_big, p_rowptr, p_col, p_perm, p_agg, N);
        combine_ln_kernel<<<cdiv(N * 32, 256), 256>>>(p_agg, p_big,
                                                      lnG + i * DD, lnB + i * DD,
                                                      p_hhi, p_hlo, N);
    }

    // --- final conv (packed [N,208]: q|k|v|sl) ---
    {
        dim3 grid(cdiv(N, TBM), 2);
        gemm_bf16x3_kernel<<<grid, 256, SMEM_WORDS * 4>>>(
            p_hhi, p_hlo, p_whi + WOFF_F, p_wlo + WOFF_F,
            p_bias + 3072, p_big, N, 208);
    }
    edge_attn_final_kernel<<<cdiv(N * 32, 256), 256>>>(p_big, p_rowptr, p_col, p_perm, p_agg, N);
    final_combine_kernel<<<cdiv(N * 16, 256), 256>>>(p_agg, p_big, flnG, flnB, out, N);
}

// round 17
// speedup vs baseline: 1.0379x; 1.0379x over previous
#include <cuda_runtime.h>
#include <cuda_bf16.h>
#include <math_constants.h>
#include <stdint.h>

// Problem constants (fixed shapes per reference)
#define MAXN 50048
#define MAXE 400000
#define DD   256

// packed weight layout (rows are output-features, k contiguous):
//   layer i (i=0..2) at i*262144 : rows 0:256=Wq^T, 256:512=Wk^T, 512:768=Wv^T, 768:1024=(Ws+linW)^T
//   final at 786432 : rows 0:64=fWq^T, 64:128=fWk^T, 128:192=fWv^T, 192:208=(fWs+flinW)^T
#define WOFF_F   786432
#define WTOTAL   (WOFF_F + 208 * 256)
#define BTOTAL   (3 * 1024 + 208)

// ---------------- scratch (static device globals; no allocs) ----------------
__device__ float g_big [MAXN * 1024];   // per-layer q|k|v|sl (stride 1024); final [N,208]
__device__ float g_agg [MAXN * DD];
__device__ __nv_bfloat16 g_hhi[MAXN * DD];
__device__ __nv_bfloat16 g_hlo[MAXN * DD];
__device__ __nv_bfloat16 g_whi[WTOTAL];
__device__ __nv_bfloat16 g_wlo[WTOTAL];
__device__ float g_bias[BTOTAL];
__device__ int   g_deg   [MAXN];
__device__ int   g_rowptr[MAXN + 1];
__device__ int   g_cursor[MAXN];
__device__ int   g_col   [MAXE];

// ---------------- CSR build ----------------
__global__ void zero_int_kernel(int* p, int n) {
    int i = blockIdx.x * blockDim.x + threadIdx.x;
    if (i < n) p[i] = 0;
}

__global__ void count_deg_kernel(const int* __restrict__ dst, int* deg, int E) {
    int i = blockIdx.x * blockDim.x + threadIdx.x;
    if (i < E) atomicAdd(&deg[dst[i]], 1);
}

// exclusive scan; writes rowptr AND cursor
__global__ void exscan_kernel(const int* __restrict__ deg, int* rowptr, int* cursor, int n) {
    __shared__ int warpsums[32];
    __shared__ int carry_s;
    int tid = threadIdx.x, lane = tid & 31, wid = tid >> 5;
    if (tid == 0) carry_s = 0;
    __syncthreads();
    for (int base = 0; base < n; base += 1024) {
        int carry = carry_s;
        int i = base + tid;
        int v = (i < n) ? deg[i] : 0;
        int x = v;
        #pragma unroll
        for (int o = 1; o < 32; o <<= 1) {
            int y = __shfl_up_sync(0xffffffffu, x, o);
            if (lane >= o) x += y;
        }
        if (lane == 31) warpsums[wid] = x;
        __syncthreads();
        if (wid == 0) {
            int s = warpsums[lane];
            #pragma unroll
            for (int o = 1; o < 32; o <<= 1) {
                int y = __shfl_up_sync(0xffffffffu, s, o);
                if (lane >= o) s += y;
            }
            warpsums[lane] = s;
        }
        __syncthreads();
        int block_excl = (wid > 0) ? warpsums[wid - 1] : 0;
        int incl = x + block_excl;
        if (i < n) {
            int val = carry + incl - v;
            rowptr[i] = val;
            cursor[i] = val;
        }
        int total = warpsums[31];
        __syncthreads();
        if (tid == 0) carry_s = carry + total;
        __syncthreads();
    }
    if (tid == 0) rowptr[n] = carry_s;
}

__global__ void scatter_kernel(const int* __restrict__ src, const int* __restrict__ dst,
                               int* cursor, int* col, int E) {
    int i = blockIdx.x * blockDim.x + threadIdx.x;
    if (i < E) {
        int d = dst[i];
        int pos = atomicAdd(&cursor[d], 1);
        col[pos] = src[i];
    }
}

// ---------------- conversions ----------------
__device__ __forceinline__ void bf16_split(float f, __nv_bfloat16& h, __nv_bfloat16& l) {
    h = __float2bfloat16(f);
    l = __float2bfloat16(f - __bfloat162float(h));
}

__global__ void convert_x_kernel(const float* __restrict__ in,
                                 __nv_bfloat16* __restrict__ hi,
                                 __nv_bfloat16* __restrict__ lo, int n) {
    int i = blockIdx.x * blockDim.x + threadIdx.x;
    if (i < n) {
        __nv_bfloat16 h, l;
        bf16_split(in[i], h, l);
        hi[i] = h; lo[i] = l;
    }
}

struct WPtrs {
    const float *Wq, *Wk, *Wv, *Ws, *linW;
    const float *fWq, *fWk, *fWv, *fWs, *flinW;
};

__global__ void convert_weights_kernel(WPtrs p, __nv_bfloat16* __restrict__ hi,
                                       __nv_bfloat16* __restrict__ lo) {
    int idx = blockIdx.x * blockDim.x + threadIdx.x;
    if (idx >= WTOTAL) return;
    float val;
    if (idx < WOFF_F) {
        int layer = idx >> 18;
        int rem = idx & 262143;
        int r = rem >> 8;
        int kk = rem & 255;
        int slot = r >> 8;
        int m = r & 255;
        size_t o = (size_t)layer * 65536 + (size_t)kk * 256 + m;
        if (slot == 0)      val = p.Wq[o];
        else if (slot == 1) val = p.Wk[o];
        else if (slot == 2) val = p.Wv[o];
        else                val = p.Ws[o] + p.linW[o];
    } else {
        int f = idx - WOFF_F;
        int r = f >> 8;
        int kk = f & 255;
        if (r < 64)       val = p.fWq[(size_t)kk * 64 + r];
        else if (r < 128) val = p.fWk[(size_t)kk * 64 + (r - 64)];
        else if (r < 192) val = p.fWv[(size_t)kk * 64 + (r - 128)];
        else              val = p.fWs[(size_t)kk * 16 + (r - 192)]
                              + p.flinW[(size_t)kk * 16 + (r - 192)];
    }
    __nv_bfloat16 h, l;
    bf16_split(val, h, l);
    hi[idx] = h; lo[idx] = l;
}

struct BPtrs {
    const float *bq, *bk, *bv, *bs, *linB;
    const float *fbq, *fbk, *fbv, *fbs, *flinB;
};

__global__ void pack_bias_kernel(BPtrs p, float* __restrict__ out) {
    int idx = blockIdx.x * blockDim.x + threadIdx.x;
    if (idx >= BTOTAL) return;
    float val;
    if (idx < 3072) {
        int layer = idx >> 10;
        int r = idx & 1023;
        int slot = r >> 8;
        int c = r & 255;
        int o = layer * 256 + c;
        if (slot == 0)      val = p.bq[o];
        else if (slot == 1) val = p.bk[o];
        else if (slot == 2) val = p.bv[o];
        else                val = p.bs[o] + p.linB[o];
    } else {
        int f = idx - 3072;
        if (f < 64)       val = p.fbq[f];
        else if (f < 128) val = p.fbk[f - 64];
        else if (f < 192) val = p.fbv[f - 128];
        else              val = p.fbs[f - 192] + p.flinB[f - 192];
    }
    out[idx] = val;
}

// ---------------- cp.async helpers ----------------
__device__ __forceinline__ void cp16(uint32_t saddr, const void* gaddr, bool pred) {
    int sz = pred ? 16 : 0;
    asm volatile("cp.async.ca.shared.global [%0], [%1], 16, %2;\n"
                 :: "r"(saddr), "l"(gaddr), "r"(sz));
}
__device__ __forceinline__ void cp_commit() {
    asm volatile("cp.async.commit_group;\n" ::: "memory");
}
template <int NN>
__device__ __forceinline__ void cp_wait() {
    asm volatile("cp.async.wait_group %0;\n" :: "n"(NN) : "memory");
}

// ---------------- mma.sync bf16x3 GEMM (R12 proven body) ----------------
#define TBM    128
#define ROW_W  20
#define A_W    (128 * ROW_W)
#define SMEM_WORDS (8 * A_W)

__device__ __forceinline__ void mma_bf16(float c[4], uint32_t a0, uint32_t a1,
                                         uint32_t a2, uint32_t a3,
                                         uint32_t b0, uint32_t b1) {
    asm volatile(
        "mma.sync.aligned.m16n8k16.row.col.f32.bf16.bf16.f32 "
        "{%0,%1,%2,%3}, {%4,%5,%6,%7}, {%8,%9}, {%0,%1,%2,%3};\n"
        : "+f"(c[0]), "+f"(c[1]), "+f"(c[2]), "+f"(c[3])
        : "r"(a0), "r"(a1), "r"(a2), "r"(a3), "r"(b0), "r"(b1));
}

__device__ __forceinline__ void ldsm_x4(uint32_t& d0, uint32_t& d1, uint32_t& d2,
                                        uint32_t& d3, uint32_t addr) {
    asm volatile("ldmatrix.sync.aligned.m8n8.x4.shared.b16 {%0,%1,%2,%3}, [%4];"
                 : "=r"(d0), "=r"(d1), "=r"(d2), "=r"(d3) : "r"(addr));
}

__global__ void __launch_bounds__(256, 2)
gemm_bf16x3_kernel(const __nv_bfloat16* __restrict__ Xhi, const __nv_bfloat16* __restrict__ Xlo,
                   const __nv_bfloat16* __restrict__ Whi, const __nv_bfloat16* __restrict__ Wlo,
                   const float* __restrict__ bias, float* __restrict__ Y,
                   int Nrows, int Mcols) {
    extern __shared__ uint32_t smw[];
    uint32_t base_u = (uint32_t)__cvta_generic_to_shared(smw);

    int tid = threadIdx.x;
    int lane = tid & 31, wid = tid >> 5;
    int rowTile = blockIdx.x * TBM;
    int colTile = blockIdx.y * 128;
    int warpRow = (wid & 3) * 32;
    int warpCol = (wid >> 2) * 64;

    float acc[2][8][4];
    #pragma unroll
    for (int mf = 0; mf < 2; mf++)
        #pragma unroll
        for (int nf = 0; nf < 8; nf++)
            #pragma unroll
            for (int i = 0; i < 4; i++) acc[mf][nf][i] = 0.f;

    auto stage = [&](int t, int buf) {
        int k0 = t * 32;
        #pragma unroll
        for (int i = 0; i < 2; i++) {
            int ch = tid + i * 256;
            int r = ch >> 2;
            int c = ch & 3;
            bool aok = (rowTile + r) < Nrows;
            size_t goff = (size_t)(rowTile + r) * 256 + k0 + c * 8;
            uint32_t soff = (uint32_t)(buf * A_W + r * ROW_W + c * 4) * 4u;
            cp16(base_u + soff, Xhi + goff, aok);
            cp16(base_u + (uint32_t)(2 * A_W) * 4u + soff, Xlo + goff, aok);
            bool bok = (colTile + r) < Mcols;
            size_t gboff = (size_t)(colTile + r) * 256 + k0 + c * 8;
            cp16(base_u + (uint32_t)(4 * A_W) * 4u + soff, Whi + gboff, bok);
            cp16(base_u + (uint32_t)(6 * A_W) * 4u + soff, Wlo + gboff, bok);
        }
        cp_commit();
    };

    stage(0, 0);

    int a_row = lane & 15;
    int a_wsel = (lane >> 4) << 2;
    int b_row = ((lane >> 4) << 3) + (lane & 7);
    int b_wsel = ((lane >> 3) & 1) << 2;

    const int NT = 8;
    for (int t = 0; t < NT; t++) {
        int buf = t & 1;
        cp_wait<0>();
        __syncthreads();
        if (t + 1 < NT) stage(t + 1, buf ^ 1);

        uint32_t AHb = base_u + (uint32_t)(buf * A_W) * 4u;
        uint32_t ALb = base_u + (uint32_t)(2 * A_W + buf * A_W) * 4u;
        uint32_t BHb = base_u + (uint32_t)(4 * A_W + buf * A_W) * 4u;
        uint32_t BLb = base_u + (uint32_t)(6 * A_W + buf * A_W) * 4u;

        #pragma unroll
        for (int s = 0; s < 2; s++) {
            int kb = s * 8;
            uint32_t ahi[2][4], alo[2][4];
            #pragma unroll
            for (int mf = 0; mf < 2; mf++) {
                uint32_t off = (uint32_t)((warpRow + mf * 16 + a_row) * ROW_W
                                          + kb + a_wsel) * 4u;
                ldsm_x4(ahi[mf][0], ahi[mf][1], ahi[mf][2], ahi[mf][3], AHb + off);
                ldsm_x4(alo[mf][0], alo[mf][1], alo[mf][2], alo[mf][3], ALb + off);
            }
            #pragma unroll
            for (int p = 0; p < 4; p++) {
                uint32_t off = (uint32_t)((warpCol + p * 16 + b_row) * ROW_W
                                          + kb + b_wsel) * 4u;
                uint32_t bh0a, bh1a, bh0b, bh1b;
                uint32_t bl0a, bl1a, bl0b, bl1b;
                ldsm_x4(bh0a, bh1a, bh0b, bh1b, BHb + off);
                ldsm_x4(bl0a, bl1a, bl0b, bl1b, BLb + off);
                #pragma unroll
                for (int mf = 0; mf < 2; mf++) {
                    mma_bf16(acc[mf][2 * p], ahi[mf][0], ahi[mf][1], ahi[mf][2], ahi[mf][3], bh0a, bh1a);
                    mma_bf16(acc[mf][2 * p], ahi[mf][0], ahi[mf][1], ahi[mf][2], ahi[mf][3], bl0a, bl1a);
                    mma_bf16(acc[mf][2 * p], alo[mf][0], alo[mf][1], alo[mf][2], alo[mf][3], bh0a, bh1a);
                }
                #pragma unroll
                for (int mf = 0; mf < 2; mf++) {
                    mma_bf16(acc[mf][2 * p + 1], ahi[mf][0], ahi[mf][1], ahi[mf][2], ahi[mf][3], bh0b, bh1b);
                    mma_bf16(acc[mf][2 * p + 1], ahi[mf][0], ahi[mf][1], ahi[mf][2], ahi[mf][3], bl0b, bl1b);
                    mma_bf16(acc[mf][2 * p + 1], alo[mf][0], alo[mf][1], alo[mf][2], alo[mf][3], bh0b, bh1b);
                }
            }
        }
    }

    #pragma unroll
    for (int mf = 0; mf < 2; mf++) {
        #pragma unroll
        for (int nf = 0; nf < 8; nf++) {
            int col = colTile + warpCol + nf * 8 + 2 * (lane & 3);
            if (col >= Mcols) continue;
            float bx = bias[col], by = bias[col + 1];
            int r0 = rowTile + warpRow + mf * 16 + (lane >> 2);
            if (r0 < Nrows) {
                float2 o = make_float2(acc[mf][nf][0] + bx, acc[mf][nf][1] + by);
                *(float2*)&Y[(size_t)r0 * Mcols + col] = o;
            }
            int r1 = r0 + 8;
            if (r1 < Nrows) {
                float2 o = make_float2(acc[mf][nf][2] + bx, acc[mf][nf][3] + by);
                *(float2*)&Y[(size_t)r1 * Mcols + col] = o;
            }
        }
    }
}

// ---------------- edge attention (layers): warp per node, all 4 heads ----------------
// Max-free streaming softmax (shift-invariant; scores O(5), exp safe).
// 128-thread blocks: block retirement waits on max warp; fewer warps/block
// lowers the expected max degree per block without touching access patterns.
__global__ void edge_attn_kernel(const float* __restrict__ big,
                                 const int* __restrict__ rowptr, const int* __restrict__ col,
                                 float* __restrict__ agg, int Nn) {
    int node = (blockIdx.x * blockDim.x + threadIdx.x) >> 5;
    int lane = threadIdx.x & 31;
    if (node >= Nn) return;
    const float* qrow = big + (size_t)node * 1024 + lane * 8;
    float4 qa = *(const float4*)qrow;
    float4 qb = *(const float4*)(qrow + 4);
    int e0 = rowptr[node], e1 = rowptr[node + 1];
    float ssum = 0.f;
    float4 acca = make_float4(0.f, 0.f, 0.f, 0.f);
    float4 accb = make_float4(0.f, 0.f, 0.f, 0.f);
    for (int e = e0; e < e1; e++) {
        int src = col[e];
        const float* kr = big + (size_t)src * 1024 + 256 + lane * 8;
        float4 ka = *(const float4*)kr;
        float4 kb = *(const float4*)(kr + 4);
        float4 va = *(const float4*)(kr + 256);
        float4 vb = *(const float4*)(kr + 260);
        float part = qa.x * ka.x + qa.y * ka.y + qa.z * ka.z + qa.w * ka.w
                   + qb.x * kb.x + qb.y * kb.y + qb.z * kb.z + qb.w * kb.w;
        part += __shfl_xor_sync(0xffffffffu, part, 1);
        part += __shfl_xor_sync(0xffffffffu, part, 2);
        part += __shfl_xor_sync(0xffffffffu, part, 4);
        float pr = __expf(part * 0.125f);      // 1/sqrt(64)
        ssum += pr;
        acca.x += pr * va.x;
        acca.y += pr * va.y;
        acca.z += pr * va.z;
        acca.w += pr * va.w;
        accb.x += pr * vb.x;
        accb.y += pr * vb.y;
        accb.z += pr * vb.z;
        accb.w += pr * vb.w;
    }
    float inv = (ssum > 0.f) ? (1.f / ssum) : 0.f;
    acca.x *= inv; acca.y *= inv; acca.z *= inv; acca.w *= inv;
    accb.x *= inv; accb.y *= inv; accb.z *= inv; accb.w *= inv;
    float* arow = agg + (size_t)node * 256 + lane * 8;
    *(float4*)arow = acca;
    *(float4*)(arow + 4) = accb;
}

// ---------------- combine + elu + layernorm -> split bf16 hi/lo ----------------
__global__ void combine_ln_kernel(const float* __restrict__ agg, const float* __restrict__ big,
                                  const float* __restrict__ g, const float* __restrict__ b,
                                  __nv_bfloat16* __restrict__ hhi,
                                  __nv_bfloat16* __restrict__ hlo, int Nn) {
    int node = (blockIdx.x * blockDim.x + threadIdx.x) >> 5;
    int lane = threadIdx.x & 31;
    if (node >= Nn) return;
    int base = node * 256;
    const float* sl = big + (size_t)node * 1024 + 768;
    float t[8];
    float sum = 0.f;
    #pragma unroll
    for (int r = 0; r < 8; r++) {
        int j = r * 32 + lane;
        float c = agg[base + j] + sl[j];
        float e = (c > 0.f) ? c : expm1f(c);
        t[r] = e; sum += e;
    }
    #pragma unroll
    for (int o = 16; o > 0; o >>= 1) sum += __shfl_xor_sync(0xffffffffu, sum, o);
    float mu = sum * (1.f / 256.f);
    float var = 0.f;
    #pragma unroll
    for (int r = 0; r < 8; r++) { float d = t[r] - mu; var += d * d; }
    #pragma unroll
    for (int o = 16; o > 0; o >>= 1) var += __shfl_xor_sync(0xffffffffu, var, o);
    var *= (1.f / 256.f);
    float inv = rsqrtf(var + 1e-5f);
    #pragma unroll
    for (int r = 0; r < 8; r++) {
        int j = r * 32 + lane;
        float val = (t[r] - mu) * inv * g[j] + b[j];
        __nv_bfloat16 h, l;
        bf16_split(val, h, l);
        hhi[base + j] = h;
        hlo[base + j] = l;
    }
}

// ---------------- final edge attention: warp per node; HF=4 heads, C=16 ch ----------------
__global__ void edge_attn_final_kernel(const float* __restrict__ big,
                                       const int* __restrict__ rowptr, const int* __restrict__ col,
                                       float* __restrict__ agg, int Nn) {
    int node = (blockIdx.x * blockDim.x + threadIdx.x) >> 5;
    int lane = threadIdx.x & 31;
    if (node >= Nn) return;
    float2 q2 = *(const float2*)(big + (size_t)node * 208 + lane * 2);
    int e0 = rowptr[node], e1 = rowptr[node + 1];
    float ssum = 0.f;
    float2 acc = make_float2(0.f, 0.f);
    for (int e = e0; e < e1; e++) {
        int src = col[e];
        const float* srow = big + (size_t)src * 208;
        float2 k2 = *(const float2*)(srow + 64 + lane * 2);
        float2 v2 = *(const float2*)(srow + 128 + lane * 2);
        float part = q2.x * k2.x + q2.y * k2.y;
        part += __shfl_xor_sync(0xffffffffu, part, 1);
        part += __shfl_xor_sync(0xffffffffu, part, 2);
        part += __shfl_xor_sync(0xffffffffu, part, 4);
        float pr = __expf(part * 0.25f);       // 1/sqrt(16)
        ssum += pr;
        acc.x += pr * v2.x;
        acc.y += pr * v2.y;
    }
    float inv = (ssum > 0.f) ? (1.f / ssum) : 0.f;
    acc.x *= inv; acc.y *= inv;
    *(float2*)(agg + (size_t)node * 64 + lane * 2) = acc;
}

// ---------------- final combine: mean heads + sl + LN(16) ----------------
__global__ void final_combine_kernel(const float* __restrict__ aggF, const float* __restrict__ big,
                                     const float* __restrict__ g, const float* __restrict__ b,
                                     float* __restrict__ out, int Nn) {
    int t = blockIdx.x * blockDim.x + threadIdx.x;
    int node = t >> 4;
    int c = t & 15;
    if (node >= Nn) return;
    const float* ar = aggF + (size_t)node * 64;
    float val = 0.25f * (ar[c] + ar[16 + c] + ar[32 + c] + ar[48 + c])
              + big[(size_t)node * 208 + 192 + c];
    float sum = val;
    #pragma unroll
    for (int o = 8; o > 0; o >>= 1) sum += __shfl_xor_sync(0xffffffffu, sum, o);
    float mu = sum * (1.f / 16.f);
    float d = val - mu;
    float var = d * d;
    #pragma unroll
    for (int o = 8; o > 0; o >>= 1) var += __shfl_xor_sync(0xffffffffu, var, o);
    var *= (1.f / 16.f);
    out[node * 16 + c] = (val - mu) * rsqrtf(var + 1e-5f) * g[c] + b[c];
}

// ---------------- host launch ----------------
static inline int cdiv(int a, int b) { return (a + b - 1) / b; }

extern "C" void kernel_launch(void* const* d_in, const int* in_sizes, int n_in,
                              void* d_out, int out_size) {
    const float* x    = (const float*)d_in[0];
    const int*   ei   = (const int*)  d_in[1];
    const float* Wq   = (const float*)d_in[2];
    const float* bq   = (const float*)d_in[3];
    const float* Wk   = (const float*)d_in[4];
    const float* bk   = (const float*)d_in[5];
    const float* Wv   = (const float*)d_in[6];
    const float* bv   = (const float*)d_in[7];
    const float* Ws   = (const float*)d_in[8];
    const float* bs   = (const float*)d_in[9];
    const float* lnG  = (const float*)d_in[10];
    const float* lnB  = (const float*)d_in[11];
    const float* linW = (const float*)d_in[12];
    const float* linB = (const float*)d_in[13];
    const float* fWq  = (const float*)d_in[14];
    const float* fbq  = (const float*)d_in[15];
    const float* fWk  = (const float*)d_in[16];
    const float* fbk  = (const float*)d_in[17];
    const float* fWv  = (const float*)d_in[18];
    const float* fbv  = (const float*)d_in[19];
    const float* fWs  = (const float*)d_in[20];
    const float* fbs  = (const float*)d_in[21];
    const float* flnG = (const float*)d_in[22];
    const float* flnB = (const float*)d_in[23];
    const float* flinW= (const float*)d_in[24];
    const float* flinB= (const float*)d_in[25];
    float* out = (float*)d_out;

    int N = in_sizes[0] / DD;     // 50000
    int E = in_sizes[1] / 2;      // 400000

    cudaFuncSetAttribute(gemm_bf16x3_kernel,
                         cudaFuncAttributeMaxDynamicSharedMemorySize, SMEM_WORDS * 4);

    float *p_big, *p_agg, *p_bias;
    __nv_bfloat16 *p_hhi, *p_hlo, *p_whi, *p_wlo;
    int *p_deg, *p_rowptr, *p_cursor, *p_col;
    cudaGetSymbolAddress((void**)&p_big,  g_big);
    cudaGetSymbolAddress((void**)&p_agg,  g_agg);
    cudaGetSymbolAddress((void**)&p_bias, g_bias);
    cudaGetSymbolAddress((void**)&p_hhi,  g_hhi);
    cudaGetSymbolAddress((void**)&p_hlo,  g_hlo);
    cudaGetSymbolAddress((void**)&p_whi,  g_whi);
    cudaGetSymbolAddress((void**)&p_wlo,  g_wlo);
    cudaGetSymbolAddress((void**)&p_deg,    g_deg);
    cudaGetSymbolAddress((void**)&p_rowptr, g_rowptr);
    cudaGetSymbolAddress((void**)&p_cursor, g_cursor);
    cudaGetSymbolAddress((void**)&p_col,    g_col);

    const int* src = ei;
    const int* dst = ei + E;

    // --- conversions first, then layer-0 GEMM (keeps GEMM in the ncu slot) ---
    WPtrs wp = { Wq, Wk, Wv, Ws, linW, fWq, fWk, fWv, fWs, flinW };
    convert_weights_kernel<<<cdiv(WTOTAL, 256), 256>>>(wp, p_whi, p_wlo);
    BPtrs bp = { bq, bk, bv, bs, linB, fbq, fbk, fbv, fbs, flinB };
    pack_bias_kernel<<<cdiv(BTOTAL, 256), 256>>>(bp, p_bias);
    convert_x_kernel<<<cdiv(N * DD, 256), 256>>>(x, p_hhi, p_hlo, N * DD);

    {   // layer-0 projections
        dim3 grid(cdiv(N, TBM), 8);
        gemm_bf16x3_kernel<<<grid, 256, SMEM_WORDS * 4>>>(
            p_hhi, p_hlo, p_whi, p_wlo, p_bias, p_big, N, 1024);
    }

    // --- CSR build (by dst) ---
    zero_int_kernel<<<cdiv(N, 256), 256>>>(p_deg, N);
    count_deg_kernel<<<cdiv(E, 256), 256>>>(dst, p_deg, E);
    exscan_kernel<<<1, 1024>>>(p_deg, p_rowptr, p_cursor, N);
    scatter_kernel<<<cdiv(E, 256), 256>>>(src, dst, p_cursor, p_col, E);

    // --- 3 TransformerConv layers (layer 0 GEMM already issued) ---
    for (int i = 0; i < 3; i++) {
        if (i > 0) {
            dim3 grid(cdiv(N, TBM), 8);
            gemm_bf16x3_kernel<<<grid, 256, SMEM_WORDS * 4>>>(
                p_hhi, p_hlo,
                p_whi + (size_t)i * 262144, p_wlo + (size_t)i * 262144,
                p_bias + i * 1024, p_big, N, 1024);
        }
        edge_attn_kernel<<<cdiv(N * 32, 128), 128>>>(p_big, p_rowptr, p_col, p_agg, N);
        combine_ln_kernel<<<cdiv(N * 32, 256), 256>>>(p_agg, p_big,
                                                      lnG + i * DD, lnB + i * DD,
                                                      p_hhi, p_hlo, N);
    }

    // --- final conv (packed [N,208]: q|k|v|sl) ---
    {
        dim3 grid(cdiv(N, TBM), 2);
        gemm_bf16x3_kernel<<<grid, 256, SMEM_WORDS * 4>>>(
            p_hhi, p_hlo, p_whi + WOFF_F, p_wlo + WOFF_F,
            p_bias + 3072, p_big, N, 208);
    }
    edge_attn_final_kernel<<<cdiv(N * 32, 128), 128>>>(p_big, p_rowptr, p_col, p_agg, N);
    final_combine_kernel<<<cdiv(N * 16, 256), 256>>>(p_agg, p_big, flnG, flnB, out, N);
}